// round 2
// baseline (speedup 1.0000x reference)
#include <cuda_runtime.h>
#include <math.h>

typedef long long LL;

// Problem constants
#define LAYERS 4
#define DM     1024        // model dim
#define NH     16          // heads
#define FF     4096        // ffn dim
#define VOC    32000
#define HD     64          // head dim
#define BB     2           // batch
#define SS     2048        // seq
#define NT     (BB*SS)     // 4096 tokens

// ---------------- scratch (static device globals; no allocation) ----------------
__device__ float g_h  [NT*DM];
__device__ float g_tmp[NT*DM];
__device__ float g_q  [NT*DM];
__device__ float g_k  [NT*DM];
__device__ float g_v  [NT*DM];
__device__ float g_ctx[NT*DM];
__device__ float g_hn [NT*DM];
__device__ float g_ffn[NT*FF];
__device__ float g_scores[(size_t)BB*NH*SS*SS];   // 512 MB

// ---------------- GEMM ----------------
// C[M,N] = act( alpha * A@B(^T) + bias )
// Batched over blockIdx.z: z -> (zb=z/Hdiv, zh=z%Hdiv), pointer offsets via strides.
__device__ __forceinline__ float gelu_exact(float x) {
    return 0.5f * x * (1.0f + erff(x * 0.70710678118654752f));
}

template<int BM, int BN, int BK, int TM, int TN, bool TRANSB, int ACT>
__global__ void gemm_k(const float* __restrict__ A, const float* __restrict__ B,
                       const float* __restrict__ bias, float* __restrict__ C,
                       int K, int lda, int ldb, int ldc, float alpha,
                       int Hdiv, LL sAb, LL sAh, LL sBb, LL sBh, LL sCb, LL sCh)
{
    constexpr int TX  = BN / TN;
    constexpr int TY  = BM / TM;
    constexpr int NTH = TX * TY;

    __shared__ float As[BK][BM + 4];
    __shared__ float Bs[BK][BN + 4];

    const int z  = blockIdx.z;
    const int zb = z / Hdiv, zh = z % Hdiv;
    A += zb * sAb + zh * sAh;
    B += zb * sBb + zh * sBh;
    C += zb * sCb + zh * sCh;

    const int m0  = blockIdx.y * BM;
    const int n0  = blockIdx.x * BN;
    const int tid = threadIdx.x;
    const int tx  = tid % TX;
    const int ty  = tid / TX;

    float acc[TM][TN];
#pragma unroll
    for (int i = 0; i < TM; i++)
#pragma unroll
        for (int j = 0; j < TN; j++) acc[i][j] = 0.0f;

    for (int k0 = 0; k0 < K; k0 += BK) {
        // A tile -> As[k][m]
#pragma unroll
        for (int r = 0; r < (BM * BK) / NTH; r++) {
            int i  = r * NTH + tid;
            int kk = i % BK;
            int m  = i / BK;
            As[kk][m] = A[(LL)(m0 + m) * lda + (k0 + kk)];
        }
        // B tile -> Bs[k][n]
#pragma unroll
        for (int r = 0; r < (BN * BK) / NTH; r++) {
            int i = r * NTH + tid;
            if (TRANSB) {
                int kk = i % BK;
                int n  = i / BK;
                Bs[kk][n] = B[(LL)(n0 + n) * ldb + (k0 + kk)];
            } else {
                int n  = i % BN;
                int kk = i / BN;
                Bs[kk][n] = B[(LL)(k0 + kk) * ldb + (n0 + n)];
            }
        }
        __syncthreads();

#pragma unroll
        for (int kk = 0; kk < BK; kk++) {
            float a[TM], b[TN];
#pragma unroll
            for (int i = 0; i < TM; i++) a[i] = As[kk][ty * TM + i];
#pragma unroll
            for (int j = 0; j < TN; j++) b[j] = Bs[kk][tx * TN + j];
#pragma unroll
            for (int i = 0; i < TM; i++)
#pragma unroll
                for (int j = 0; j < TN; j++)
                    acc[i][j] = fmaf(a[i], b[j], acc[i][j]);
        }
        __syncthreads();
    }

#pragma unroll
    for (int i = 0; i < TM; i++) {
        int m = m0 + ty * TM + i;
#pragma unroll
        for (int j = 0; j < TN; j++) {
            int n = n0 + tx * TN + j;
            float val = acc[i][j] * alpha;
            if (bias) val += bias[n];
            if (ACT == 1) val = gelu_exact(val);
            C[(LL)m * ldc + n] = val;
        }
    }
}

// ---------------- softmax over rows of length 2048 ----------------
__global__ void softmax2048_k(float* __restrict__ sc)
{
    __shared__ float red[32];
    float* p = sc + (LL)blockIdx.x * 2048;
    const int tid = threadIdx.x;            // 256 threads
    float v[8];
    float mx = -1e30f;
#pragma unroll
    for (int i = 0; i < 8; i++) { v[i] = p[tid + i * 256]; mx = fmaxf(mx, v[i]); }
#pragma unroll
    for (int o = 16; o > 0; o >>= 1) mx = fmaxf(mx, __shfl_xor_sync(0xffffffffu, mx, o));
    if ((tid & 31) == 0) red[tid >> 5] = mx;
    __syncthreads();
    if (tid < 32) {
        float t = (tid < 8) ? red[tid] : -1e30f;
#pragma unroll
        for (int o = 4; o > 0; o >>= 1) t = fmaxf(t, __shfl_xor_sync(0xffffffffu, t, o));
        if (tid == 0) red[0] = t;
    }
    __syncthreads();
    mx = red[0];
    __syncthreads();

    float s = 0.0f;
#pragma unroll
    for (int i = 0; i < 8; i++) { v[i] = __expf(v[i] - mx); s += v[i]; }
#pragma unroll
    for (int o = 16; o > 0; o >>= 1) s += __shfl_xor_sync(0xffffffffu, s, o);
    if ((tid & 31) == 0) red[tid >> 5] = s;
    __syncthreads();
    if (tid < 32) {
        float t = (tid < 8) ? red[tid] : 0.0f;
#pragma unroll
        for (int o = 4; o > 0; o >>= 1) t += __shfl_xor_sync(0xffffffffu, t, o);
        if (tid == 0) red[0] = t;
    }
    __syncthreads();
    float inv = 1.0f / red[0];
#pragma unroll
    for (int i = 0; i < 8; i++) p[tid + i * 256] = v[i] * inv;
}

// ---------------- residual add + layernorm (row of 1024) ----------------
__global__ void add_ln_k(const float* __restrict__ x, const float* __restrict__ r,
                         const float* __restrict__ g, const float* __restrict__ b,
                         float* __restrict__ o)
{
    __shared__ float redS[8];
    __shared__ float redQ[8];
    const LL row = blockIdx.x;
    const float* px = x + row * DM;
    const float* pr = r ? (r + row * DM) : nullptr;
    const int tid = threadIdx.x;            // 256 threads
    float v[4];
    float s = 0.0f, sq = 0.0f;
#pragma unroll
    for (int i = 0; i < 4; i++) {
        float t = px[tid + i * 256];
        if (pr) t += pr[tid + i * 256];
        v[i] = t;
        s += t;
        sq = fmaf(t, t, sq);
    }
#pragma unroll
    for (int off = 16; off > 0; off >>= 1) {
        s  += __shfl_xor_sync(0xffffffffu, s,  off);
        sq += __shfl_xor_sync(0xffffffffu, sq, off);
    }
    if ((tid & 31) == 0) { redS[tid >> 5] = s; redQ[tid >> 5] = sq; }
    __syncthreads();
    if (tid < 32) {
        float ts = (tid < 8) ? redS[tid] : 0.0f;
        float tq = (tid < 8) ? redQ[tid] : 0.0f;
#pragma unroll
        for (int off = 4; off > 0; off >>= 1) {
            ts += __shfl_xor_sync(0xffffffffu, ts, off);
            tq += __shfl_xor_sync(0xffffffffu, tq, off);
        }
        if (tid == 0) { redS[0] = ts; redQ[0] = tq; }
    }
    __syncthreads();
    const float mean = redS[0] * (1.0f / DM);
    const float var  = redQ[0] * (1.0f / DM) - mean * mean;
    const float rstd = rsqrtf(var + 1e-5f);
    float* po = o + row * DM;
#pragma unroll
    for (int i = 0; i < 4; i++) {
        int d = tid + i * 256;
        po[d] = (v[i] - mean) * rstd * g[d] + b[d];
    }
}

// ---------------- embedding + positional (h = 2*tok + pe) ----------------
__global__ void embed_k(const int* __restrict__ ids, const float* __restrict__ emb,
                        const float* __restrict__ pe, float* __restrict__ h)
{
    int idx = blockIdx.x * 256 + threadIdx.x;     // total NT*DM
    int t = idx >> 10;
    int d = idx & 1023;
    int sp = t & (SS - 1);
    h[idx] = 2.0f * emb[(LL)ids[t] * DM + d] + pe[(LL)sp * DM + d];
}

// ---------------- host driver ----------------
extern "C" void kernel_launch(void* const* d_in, const int* in_sizes, int n_in,
                              void* d_out, int out_size)
{
    (void)in_sizes; (void)n_in; (void)out_size;

    const int*   ids  = (const int*)  d_in[0];
    const float* emb  = (const float*)d_in[1];
    const float* pe   = (const float*)d_in[2];
    const float* wq   = (const float*)d_in[3];
    const float* bq   = (const float*)d_in[4];
    const float* wk   = (const float*)d_in[5];
    const float* bk   = (const float*)d_in[6];
    const float* wv   = (const float*)d_in[7];
    const float* bv   = (const float*)d_in[8];
    const float* wo   = (const float*)d_in[9];
    const float* bo   = (const float*)d_in[10];
    const float* ln1g = (const float*)d_in[11];
    const float* ln1b = (const float*)d_in[12];
    const float* w1   = (const float*)d_in[13];
    const float* b1   = (const float*)d_in[14];
    const float* w2   = (const float*)d_in[15];
    const float* b2   = (const float*)d_in[16];
    const float* ln2g = (const float*)d_in[17];
    const float* ln2b = (const float*)d_in[18];
    const float* lnfg = (const float*)d_in[19];
    const float* lnfb = (const float*)d_in[20];
    const float* lmh  = (const float*)d_in[21];
    float* out = (float*)d_out;

    float *h, *tmp, *q, *k, *v, *ctx, *hn, *ffn, *sc;
    cudaGetSymbolAddress((void**)&h,   g_h);
    cudaGetSymbolAddress((void**)&tmp, g_tmp);
    cudaGetSymbolAddress((void**)&q,   g_q);
    cudaGetSymbolAddress((void**)&k,   g_k);
    cudaGetSymbolAddress((void**)&v,   g_v);
    cudaGetSymbolAddress((void**)&ctx, g_ctx);
    cudaGetSymbolAddress((void**)&hn,  g_hn);
    cudaGetSymbolAddress((void**)&ffn, g_ffn);
    cudaGetSymbolAddress((void**)&sc,  g_scores);

    // h = 2*tok + pe
    embed_k<<<(NT * DM) / 256, 256>>>(ids, emb, pe, h);

    const float scale = 1.0f / 8.0f;   // 1/sqrt(64)

    for (int i = 0; i < LAYERS; i++) {
        const float* wqi = wq + (LL)i * DM * DM;  const float* bqi = bq + (LL)i * DM;
        const float* wki = wk + (LL)i * DM * DM;  const float* bki = bk + (LL)i * DM;
        const float* wvi = wv + (LL)i * DM * DM;  const float* bvi = bv + (LL)i * DM;
        const float* woi = wo + (LL)i * DM * DM;  const float* boi = bo + (LL)i * DM;
        const float* w1i = w1 + (LL)i * DM * FF;  const float* b1i = b1 + (LL)i * FF;
        const float* w2i = w2 + (LL)i * FF * DM;  const float* b2i = b2 + (LL)i * DM;

        // Q/K/V projections: [4096,1024] = h @ W + b
        {
            dim3 grid(DM / 128, NT / 128, 1);
            gemm_k<128,128,8,8,8,false,0><<<grid, 256>>>(h, wqi, bqi, q, DM, DM, DM, DM, 1.0f,
                                                         1, 0,0, 0,0, 0,0);
            gemm_k<128,128,8,8,8,false,0><<<grid, 256>>>(h, wki, bki, k, DM, DM, DM, DM, 1.0f,
                                                         1, 0,0, 0,0, 0,0);
            gemm_k<128,128,8,8,8,false,0><<<grid, 256>>>(h, wvi, bvi, v, DM, DM, DM, DM, 1.0f,
                                                         1, 0,0, 0,0, 0,0);
        }

        // scores[z] = scale * Qh @ Kh^T   (batched over z = b*NH + hh)
        {
            dim3 grid(SS / 128, SS / 128, BB * NH);
            gemm_k<128,128,8,8,8,true,0><<<grid, 256>>>(
                q, k, nullptr, sc, HD, DM, DM, SS, scale,
                NH, (LL)SS * DM, HD, (LL)SS * DM, HD,
                (LL)NH * SS * SS, (LL)SS * SS);
        }

        // softmax rows
        softmax2048_k<<<BB * NH * SS, 256>>>(sc);

        // ctx[z] = P @ Vh  -> write to [b, s, hh*64 + d] layout
        {
            dim3 grid(HD / 64, SS / 128, BB * NH);
            gemm_k<128,64,8,8,4,false,0><<<grid, 256>>>(
                sc, v, nullptr, ctx, SS, SS, DM, DM, 1.0f,
                NH, (LL)NH * SS * SS, (LL)SS * SS,
                (LL)SS * DM, HD, (LL)SS * DM, HD);
        }

        // attn_out = ctx @ wo + bo
        {
            dim3 grid(DM / 128, NT / 128, 1);
            gemm_k<128,128,8,8,8,false,0><<<grid, 256>>>(ctx, woi, boi, tmp, DM, DM, DM, DM, 1.0f,
                                                         1, 0,0, 0,0, 0,0);
        }
        // h = LN(h + attn_out)
        add_ln_k<<<NT, 256>>>(h, tmp, ln1g + (LL)i * DM, ln1b + (LL)i * DM, h);

        // ffn1 = gelu(h @ w1 + b1)
        {
            dim3 grid(FF / 128, NT / 128, 1);
            gemm_k<128,128,8,8,8,false,1><<<grid, 256>>>(h, w1i, b1i, ffn, DM, DM, FF, FF, 1.0f,
                                                         1, 0,0, 0,0, 0,0);
        }
        // ffn2 = ffn1 @ w2 + b2
        {
            dim3 grid(DM / 128, NT / 128, 1);
            gemm_k<128,128,8,8,8,false,0><<<grid, 256>>>(ffn, w2i, b2i, tmp, FF, FF, DM, DM, 1.0f,
                                                         1, 0,0, 0,0, 0,0);
        }
        // h = LN(h + ffn2)
        add_ln_k<<<NT, 256>>>(h, tmp, ln2g + (LL)i * DM, ln2b + (LL)i * DM, h);
    }

    // final LN
    add_ln_k<<<NT, 256>>>(h, nullptr, lnfg, lnfb, hn);

    // logits = hn @ lm_head   [4096, 32000]
    {
        dim3 grid(VOC / 128, NT / 128, 1);
        gemm_k<128,128,8,8,8,false,0><<<grid, 256>>>(hn, lmh, nullptr, out, DM, DM, VOC, VOC, 1.0f,
                                                     1, 0,0, 0,0, 0,0);
    }
}

// round 8
// speedup vs baseline: 1.3520x; 1.3520x over previous
#include <cuda_runtime.h>
#include <math.h>

typedef long long LL;

#define LAYERS 4
#define DM     1024
#define NH     16
#define FF     4096
#define VOC    32000
#define HD     64
#define BB     2
#define SS     2048
#define NT     (BB*SS)

// ---------------- scratch (static device globals; no allocation) ----------------
__device__ float g_h  [NT*DM];
__device__ float g_tmp[NT*DM];
__device__ float g_q  [NT*DM];
__device__ float g_k  [NT*DM];
__device__ float g_v  [NT*DM];
__device__ float g_ctx[NT*DM];
__device__ float g_hn [NT*DM];
__device__ float g_ffn[NT*FF];
__device__ float g_scores[(size_t)BB*NH*SS*SS];

__device__ __forceinline__ float gelu_exact(float x) {
    return 0.5f * x * (1.0f + erff(x * 0.70710678118654752f));
}

__device__ __forceinline__ void cp16(float* s, const float* g) {
    unsigned sa = (unsigned)__cvta_generic_to_shared(s);
    asm volatile("cp.async.cg.shared.global [%0], [%1], 16;\n" :: "r"(sa), "l"(g));
}
__device__ __forceinline__ void cp_commit() { asm volatile("cp.async.commit_group;\n"); }
__device__ __forceinline__ void cp_wait0()  { asm volatile("cp.async.wait_group 0;\n"); }

__device__ __forceinline__ unsigned tf32_rna(float x) {
    unsigned u;
    asm("cvt.rna.tf32.f32 %0, %1;\n" : "=r"(u) : "f"(x));
    return u;
}
// split x into hi (tf32) and lo (tf32 of remainder)
__device__ __forceinline__ void tf32_split(float x, unsigned& hi, unsigned& lo) {
    hi = tf32_rna(x);
    lo = tf32_rna(x - __uint_as_float(hi));
}

__device__ __forceinline__ void mma_tf32(float c[4], const unsigned a[4], const unsigned b[2]) {
    asm volatile(
        "mma.sync.aligned.m16n8k8.row.col.f32.tf32.tf32.f32 "
        "{%0,%1,%2,%3}, {%4,%5,%6,%7}, {%8,%9}, {%0,%1,%2,%3};\n"
        : "+f"(c[0]), "+f"(c[1]), "+f"(c[2]), "+f"(c[3])
        : "r"(a[0]), "r"(a[1]), "r"(a[2]), "r"(a[3]), "r"(b[0]), "r"(b[1]));
}

// ---------------- 3xTF32 tensor-core GEMM (near-fp32 accuracy) ----------------
// C[M,N] = act( alpha * A@B(^T) + bias ), batched over blockIdx.z
template<int BM, int BN, int BK, int WM, int WN, bool TRANSB, int ACT>
__global__ void __launch_bounds__(256)
mma_gemm(const float* __restrict__ A, const float* __restrict__ B,
         const float* __restrict__ bias, float* __restrict__ C,
         int K, int lda, int ldb, int ldc, float alpha,
         int Hdiv, LL sAb, LL sAh, LL sBb, LL sBh, LL sCb, LL sCh)
{
    constexpr int WARPS_M = BM / WM;
    constexpr int WARPS_N = BN / WN;
    constexpr int NTH = WARPS_M * WARPS_N * 32;
    constexpr int MT = WM / 16;
    constexpr int NTt = WN / 8;
    constexpr int AP  = BK + 4;
    constexpr int BPn = BN + 8;
    constexpr int BPt = BK + 4;
    constexpr int ASZ = BM * AP;
    constexpr int BSZ = TRANSB ? (BN * BPt) : (BK * BPn);

    __shared__ float sm[2 * ASZ + 2 * BSZ];

    const int z  = blockIdx.z;
    const int zb = z / Hdiv, zh = z % Hdiv;
    A += zb * sAb + zh * sAh;
    B += zb * sBb + zh * sBh;
    C += zb * sCb + zh * sCh;

    const int m0  = blockIdx.y * BM;
    const int n0  = blockIdx.x * BN;
    const int tid = threadIdx.x;
    const int warp = tid >> 5;
    const int lane = tid & 31;
    const int gr  = lane >> 2;
    const int tg  = lane & 3;
    const int wm0 = (warp / WARPS_N) * WM;
    const int wn0 = (warp % WARPS_N) * WN;

    float acc[MT][NTt][4];
#pragma unroll
    for (int i = 0; i < MT; i++)
#pragma unroll
        for (int j = 0; j < NTt; j++)
#pragma unroll
            for (int q = 0; q < 4; q++) acc[i][j][q] = 0.0f;

    auto loadTiles = [&](int kt, int buf) {
        const int k0 = kt * BK;
        float* Asp = sm + buf * ASZ;
        float* Bsp = sm + 2 * ASZ + buf * BSZ;
#pragma unroll
        for (int r = 0; r < (BM * BK / 4) / NTH; r++) {
            int idx = r * NTH + tid;
            int m = idx / (BK / 4), k4 = idx % (BK / 4);
            cp16(&Asp[m * AP + k4 * 4], &A[(LL)(m0 + m) * lda + k0 + k4 * 4]);
        }
        if (TRANSB) {
#pragma unroll
            for (int r = 0; r < (BN * BK / 4) / NTH; r++) {
                int idx = r * NTH + tid;
                int n = idx / (BK / 4), k4 = idx % (BK / 4);
                cp16(&Bsp[n * BPt + k4 * 4], &B[(LL)(n0 + n) * ldb + k0 + k4 * 4]);
            }
        } else {
#pragma unroll
            for (int r = 0; r < (BK * BN / 4) / NTH; r++) {
                int idx = r * NTH + tid;
                int kk = idx / (BN / 4), n4 = idx % (BN / 4);
                cp16(&Bsp[kk * BPn + n4 * 4], &B[(LL)(k0 + kk) * ldb + n0 + n4 * 4]);
            }
        }
        cp_commit();
    };

    auto compute = [&](int buf) {
        const float* Asp = sm + buf * ASZ;
        const float* Bsp = sm + 2 * ASZ + buf * BSZ;
#pragma unroll
        for (int ks = 0; ks < BK; ks += 8) {
            unsigned ah[MT][4], al[MT][4], bh[NTt][2], bl[NTt][2];
#pragma unroll
            for (int mt = 0; mt < MT; mt++) {
                int m = wm0 + mt * 16;
                float x0 = Asp[(m + gr) * AP + ks + tg];
                float x1 = Asp[(m + gr + 8) * AP + ks + tg];
                float x2 = Asp[(m + gr) * AP + ks + tg + 4];
                float x3 = Asp[(m + gr + 8) * AP + ks + tg + 4];
                tf32_split(x0, ah[mt][0], al[mt][0]);
                tf32_split(x1, ah[mt][1], al[mt][1]);
                tf32_split(x2, ah[mt][2], al[mt][2]);
                tf32_split(x3, ah[mt][3], al[mt][3]);
            }
#pragma unroll
            for (int nt = 0; nt < NTt; nt++) {
                int n = wn0 + nt * 8;
                float y0, y1;
                if (TRANSB) {
                    y0 = Bsp[(n + gr) * BPt + ks + tg];
                    y1 = Bsp[(n + gr) * BPt + ks + tg + 4];
                } else {
                    y0 = Bsp[(ks + tg) * BPn + n + gr];
                    y1 = Bsp[(ks + tg + 4) * BPn + n + gr];
                }
                tf32_split(y0, bh[nt][0], bl[nt][0]);
                tf32_split(y1, bh[nt][1], bl[nt][1]);
            }
            // 3xTF32: hi*hi + hi*lo + lo*hi  (lo*lo ~2^-22, dropped)
#pragma unroll
            for (int mt = 0; mt < MT; mt++)
#pragma unroll
                for (int nt = 0; nt < NTt; nt++) {
                    mma_tf32(acc[mt][nt], ah[mt], bl[nt]);
                    mma_tf32(acc[mt][nt], al[mt], bh[nt]);
                    mma_tf32(acc[mt][nt], ah[mt], bh[nt]);
                }
        }
    };

    const int KT = K / BK;
    loadTiles(0, 0);
    for (int kt = 0; kt < KT; kt++) {
        cp_wait0();
        __syncthreads();
        if (kt + 1 < KT) loadTiles(kt + 1, (kt + 1) & 1);
        compute(kt & 1);
        __syncthreads();
    }

    // epilogue
#pragma unroll
    for (int mt = 0; mt < MT; mt++) {
        int r0 = m0 + wm0 + mt * 16 + gr;
#pragma unroll
        for (int nt = 0; nt < NTt; nt++) {
            int cc = n0 + wn0 + nt * 8 + tg * 2;
            float v0 = acc[mt][nt][0] * alpha;
            float v1 = acc[mt][nt][1] * alpha;
            float v2 = acc[mt][nt][2] * alpha;
            float v3 = acc[mt][nt][3] * alpha;
            if (bias) {
                float b0 = bias[cc], b1 = bias[cc + 1];
                v0 += b0; v1 += b1; v2 += b0; v3 += b1;
            }
            if (ACT == 1) {
                v0 = gelu_exact(v0); v1 = gelu_exact(v1);
                v2 = gelu_exact(v2); v3 = gelu_exact(v3);
            }
            float2 p0 = {v0, v1};
            float2 p1 = {v2, v3};
            *reinterpret_cast<float2*>(&C[(LL)r0 * ldc + cc]) = p0;
            *reinterpret_cast<float2*>(&C[(LL)(r0 + 8) * ldc + cc]) = p1;
        }
    }
}

// ---------------- softmax over rows of length 2048 ----------------
__global__ void softmax2048_k(float* __restrict__ sc)
{
    __shared__ float red[32];
    float* p = sc + (LL)blockIdx.x * 2048;
    const int tid = threadIdx.x;
    float v[8];
    float mx = -1e30f;
#pragma unroll
    for (int i = 0; i < 8; i++) { v[i] = p[tid + i * 256]; mx = fmaxf(mx, v[i]); }
#pragma unroll
    for (int o = 16; o > 0; o >>= 1) mx = fmaxf(mx, __shfl_xor_sync(0xffffffffu, mx, o));
    if ((tid & 31) == 0) red[tid >> 5] = mx;
    __syncthreads();
    if (tid < 32) {
        float t = (tid < 8) ? red[tid] : -1e30f;
#pragma unroll
        for (int o = 4; o > 0; o >>= 1) t = fmaxf(t, __shfl_xor_sync(0xffffffffu, t, o));
        if (tid == 0) red[0] = t;
    }
    __syncthreads();
    mx = red[0];
    __syncthreads();

    float s = 0.0f;
#pragma unroll
    for (int i = 0; i < 8; i++) { v[i] = __expf(v[i] - mx); s += v[i]; }
#pragma unroll
    for (int o = 16; o > 0; o >>= 1) s += __shfl_xor_sync(0xffffffffu, s, o);
    if ((tid & 31) == 0) red[tid >> 5] = s;
    __syncthreads();
    if (tid < 32) {
        float t = (tid < 8) ? red[tid] : 0.0f;
#pragma unroll
        for (int o = 4; o > 0; o >>= 1) t += __shfl_xor_sync(0xffffffffu, t, o);
        if (tid == 0) red[0] = t;
    }
    __syncthreads();
    float inv = 1.0f / red[0];
#pragma unroll
    for (int i = 0; i < 8; i++) p[tid + i * 256] = v[i] * inv;
}

// ---------------- residual add + layernorm ----------------
__global__ void add_ln_k(const float* __restrict__ x, const float* __restrict__ r,
                         const float* __restrict__ g, const float* __restrict__ b,
                         float* __restrict__ o)
{
    __shared__ float redS[8];
    __shared__ float redQ[8];
    const LL row = blockIdx.x;
    const float* px = x + row * DM;
    const float* pr = r ? (r + row * DM) : nullptr;
    const int tid = threadIdx.x;
    float v[4];
    float s = 0.0f, sq = 0.0f;
#pragma unroll
    for (int i = 0; i < 4; i++) {
        float t = px[tid + i * 256];
        if (pr) t += pr[tid + i * 256];
        v[i] = t;
        s += t;
        sq = fmaf(t, t, sq);
    }
#pragma unroll
    for (int off = 16; off > 0; off >>= 1) {
        s  += __shfl_xor_sync(0xffffffffu, s,  off);
        sq += __shfl_xor_sync(0xffffffffu, sq, off);
    }
    if ((tid & 31) == 0) { redS[tid >> 5] = s; redQ[tid >> 5] = sq; }
    __syncthreads();
    if (tid < 32) {
        float ts = (tid < 8) ? redS[tid] : 0.0f;
        float tq = (tid < 8) ? redQ[tid] : 0.0f;
#pragma unroll
        for (int off = 4; off > 0; off >>= 1) {
            ts += __shfl_xor_sync(0xffffffffu, ts, off);
            tq += __shfl_xor_sync(0xffffffffu, tq, off);
        }
        if (tid == 0) { redS[0] = ts; redQ[0] = tq; }
    }
    __syncthreads();
    const float mean = redS[0] * (1.0f / DM);
    const float var  = redQ[0] * (1.0f / DM) - mean * mean;
    const float rstd = rsqrtf(var + 1e-5f);
    float* po = o + row * DM;
#pragma unroll
    for (int i = 0; i < 4; i++) {
        int d = tid + i * 256;
        po[d] = (v[i] - mean) * rstd * g[d] + b[d];
    }
}

// ---------------- embedding + positional ----------------
__global__ void embed_k(const int* __restrict__ ids, const float* __restrict__ emb,
                        const float* __restrict__ pe, float* __restrict__ h)
{
    int idx = blockIdx.x * 256 + threadIdx.x;
    int t = idx >> 10;
    int d = idx & 1023;
    int sp = t & (SS - 1);
    h[idx] = 2.0f * emb[(LL)ids[t] * DM + d] + pe[(LL)sp * DM + d];
}

// ---------------- host driver ----------------
extern "C" void kernel_launch(void* const* d_in, const int* in_sizes, int n_in,
                              void* d_out, int out_size)
{
    (void)in_sizes; (void)n_in; (void)out_size;

    const int*   ids  = (const int*)  d_in[0];
    const float* emb  = (const float*)d_in[1];
    const float* pe   = (const float*)d_in[2];
    const float* wq   = (const float*)d_in[3];
    const float* bq   = (const float*)d_in[4];
    const float* wk   = (const float*)d_in[5];
    const float* bk   = (const float*)d_in[6];
    const float* wv   = (const float*)d_in[7];
    const float* bv   = (const float*)d_in[8];
    const float* wo   = (const float*)d_in[9];
    const float* bo   = (const float*)d_in[10];
    const float* ln1g = (const float*)d_in[11];
    const float* ln1b = (const float*)d_in[12];
    const float* w1   = (const float*)d_in[13];
    const float* b1   = (const float*)d_in[14];
    const float* w2   = (const float*)d_in[15];
    const float* b2   = (const float*)d_in[16];
    const float* ln2g = (const float*)d_in[17];
    const float* ln2b = (const float*)d_in[18];
    const float* lnfg = (const float*)d_in[19];
    const float* lnfb = (const float*)d_in[20];
    const float* lmh  = (const float*)d_in[21];
    float* out = (float*)d_out;

    float *h, *tmp, *q, *k, *v, *ctx, *hn, *ffn, *sc;
    cudaGetSymbolAddress((void**)&h,   g_h);
    cudaGetSymbolAddress((void**)&tmp, g_tmp);
    cudaGetSymbolAddress((void**)&q,   g_q);
    cudaGetSymbolAddress((void**)&k,   g_k);
    cudaGetSymbolAddress((void**)&v,   g_v);
    cudaGetSymbolAddress((void**)&ctx, g_ctx);
    cudaGetSymbolAddress((void**)&hn,  g_hn);
    cudaGetSymbolAddress((void**)&ffn, g_ffn);
    cudaGetSymbolAddress((void**)&sc,  g_scores);

    embed_k<<<(NT * DM) / 256, 256>>>(ids, emb, pe, h);

    const float scale = 1.0f / 8.0f;

    for (int i = 0; i < LAYERS; i++) {
        const float* wqi = wq + (LL)i * DM * DM;  const float* bqi = bq + (LL)i * DM;
        const float* wki = wk + (LL)i * DM * DM;  const float* bki = bk + (LL)i * DM;
        const float* wvi = wv + (LL)i * DM * DM;  const float* bvi = bv + (LL)i * DM;
        const float* woi = wo + (LL)i * DM * DM;  const float* boi = bo + (LL)i * DM;
        const float* w1i = w1 + (LL)i * DM * FF;  const float* b1i = b1 + (LL)i * FF;
        const float* w2i = w2 + (LL)i * FF * DM;  const float* b2i = b2 + (LL)i * DM;

        // Q/K/V projections
        {
            dim3 grid(DM / 128, NT / 128, 1);
            mma_gemm<128,128,16,64,32,false,0><<<grid, 256>>>(h, wqi, bqi, q, DM, DM, DM, DM, 1.0f,
                                                              1, 0,0, 0,0, 0,0);
            mma_gemm<128,128,16,64,32,false,0><<<grid, 256>>>(h, wki, bki, k, DM, DM, DM, DM, 1.0f,
                                                              1, 0,0, 0,0, 0,0);
            mma_gemm<128,128,16,64,32,false,0><<<grid, 256>>>(h, wvi, bvi, v, DM, DM, DM, DM, 1.0f,
                                                              1, 0,0, 0,0, 0,0);
        }

        // scores[z] = scale * Qh @ Kh^T
        {
            dim3 grid(SS / 128, SS / 128, BB * NH);
            mma_gemm<128,128,16,64,32,true,0><<<grid, 256>>>(
                q, k, nullptr, sc, HD, DM, DM, SS, scale,
                NH, (LL)SS * DM, HD, (LL)SS * DM, HD,
                (LL)NH * SS * SS, (LL)SS * SS);
        }

        softmax2048_k<<<BB * NH * SS, 256>>>(sc);

        // ctx[z] = P @ Vh
        {
            dim3 grid(HD / 64, SS / 128, BB * NH);
            mma_gemm<128,64,16,32,32,false,0><<<grid, 256>>>(
                sc, v, nullptr, ctx, SS, SS, DM, DM, 1.0f,
                NH, (LL)NH * SS * SS, (LL)SS * SS,
                (LL)SS * DM, HD, (LL)SS * DM, HD);
        }

        // attn_out = ctx @ wo + bo
        {
            dim3 grid(DM / 128, NT / 128, 1);
            mma_gemm<128,128,16,64,32,false,0><<<grid, 256>>>(ctx, woi, boi, tmp, DM, DM, DM, DM, 1.0f,
                                                              1, 0,0, 0,0, 0,0);
        }
        add_ln_k<<<NT, 256>>>(h, tmp, ln1g + (LL)i * DM, ln1b + (LL)i * DM, h);

        // ffn1 = gelu(h @ w1 + b1)
        {
            dim3 grid(FF / 128, NT / 128, 1);
            mma_gemm<128,128,16,64,32,false,1><<<grid, 256>>>(h, w1i, b1i, ffn, DM, DM, FF, FF, 1.0f,
                                                              1, 0,0, 0,0, 0,0);
        }
        // ffn2 = ffn1 @ w2 + b2
        {
            dim3 grid(DM / 128, NT / 128, 1);
            mma_gemm<128,128,16,64,32,false,0><<<grid, 256>>>(ffn, w2i, b2i, tmp, FF, FF, DM, DM, 1.0f,
                                                              1, 0,0, 0,0, 0,0);
        }
        add_ln_k<<<NT, 256>>>(h, tmp, ln2g + (LL)i * DM, ln2b + (LL)i * DM, h);
    }

    add_ln_k<<<NT, 256>>>(h, nullptr, lnfg, lnfb, hn);

    // logits = hn @ lm_head
    {
        dim3 grid(VOC / 128, NT / 128, 1);
        mma_gemm<128,128,16,64,32,false,0><<<grid, 256>>>(hn, lmh, nullptr, out, DM, DM, VOC, VOC, 1.0f,
                                                          1, 0,0, 0,0, 0,0);
    }
}

// round 10
// speedup vs baseline: 2.7257x; 2.0161x over previous
#include <cuda_runtime.h>
#include <math.h>

typedef long long LL;

#define LAYERS 4
#define DM     1024
#define NH     16
#define FF     4096
#define VOC    32000
#define HD     64
#define BB     2
#define SS     2048
#define NT     (BB*SS)

// ---------------- scratch (static device globals; no allocation) ----------------
__device__ float g_h  [NT*DM];
__device__ float g_tmp[NT*DM];
__device__ float g_q  [NT*DM];
__device__ float g_k  [NT*DM];
__device__ float g_v  [NT*DM];
__device__ float g_ctx[NT*DM];
__device__ float g_hn [NT*DM];
__device__ float g_ffn[NT*FF];
__device__ float g_scores[(size_t)BB*NH*SS*SS];

__device__ __forceinline__ float gelu_exact(float x) {
    return 0.5f * x * (1.0f + erff(x * 0.70710678118654752f));
}

__device__ __forceinline__ void cp16(float* s, const float* g) {
    unsigned sa = (unsigned)__cvta_generic_to_shared(s);
    asm volatile("cp.async.cg.shared.global [%0], [%1], 16;\n" :: "r"(sa), "l"(g));
}
__device__ __forceinline__ void cp_commit() { asm volatile("cp.async.commit_group;\n"); }
__device__ __forceinline__ void cp_wait0()  { asm volatile("cp.async.wait_group 0;\n"); }

// split packed pair (x0,x1) into bf16x2 hi and bf16x2 lo (lo = x - hi)
__device__ __forceinline__ void bf16x2_split(float x0, float x1, unsigned& hi, unsigned& lo) {
    asm("cvt.rn.bf16x2.f32 %0, %1, %2;\n" : "=r"(hi) : "f"(x1), "f"(x0));
    float h0 = __uint_as_float(hi << 16);
    float h1 = __uint_as_float(hi & 0xffff0000u);
    float l0 = x0 - h0;
    float l1 = x1 - h1;
    asm("cvt.rn.bf16x2.f32 %0, %1, %2;\n" : "=r"(lo) : "f"(l1), "f"(l0));
}

__device__ __forceinline__ void mma_bf16(float c[4], const unsigned a[4], const unsigned b[2]) {
    asm volatile(
        "mma.sync.aligned.m16n8k16.row.col.f32.bf16.bf16.f32 "
        "{%0,%1,%2,%3}, {%4,%5,%6,%7}, {%8,%9}, {%0,%1,%2,%3};\n"
        : "+f"(c[0]), "+f"(c[1]), "+f"(c[2]), "+f"(c[3])
        : "r"(a[0]), "r"(a[1]), "r"(a[2]), "r"(a[3]), "r"(b[0]), "r"(b[1]));
}

// ---------------- 3xBF16 tensor-core GEMM (near-fp32 accuracy) ----------------
// C[M,N] = act( alpha * A@B(^T) + bias ), batched over blockIdx.z
template<int BM, int BN, int BK, int WM, int WN, bool TRANSB, int ACT>
__global__ void __launch_bounds__(256)
mma_gemm(const float* __restrict__ A, const float* __restrict__ B,
         const float* __restrict__ bias, float* __restrict__ C,
         int K, int lda, int ldb, int ldc, float alpha,
         int Hdiv, LL sAb, LL sAh, LL sBb, LL sBh, LL sCb, LL sCh)
{
    constexpr int WARPS_M = BM / WM;
    constexpr int WARPS_N = BN / WN;
    constexpr int NTH = WARPS_M * WARPS_N * 32;
    constexpr int MT  = WM / 16;
    constexpr int NTt = WN / 8;
    constexpr int AP  = BK + 8;                 // A smem row stride (float2-conflict-free)
    constexpr int BPn = BN + 12;                // B notrans row stride
    constexpr int BPt = BK + 8;                 // B trans row stride
    constexpr int ASZ = BM * AP;
    constexpr int BSZ = TRANSB ? (BN * BPt) : (BK * BPn);

    __shared__ float sm[2 * ASZ + 2 * BSZ];

    const int z  = blockIdx.z;
    const int zb = z / Hdiv, zh = z % Hdiv;
    A += zb * sAb + zh * sAh;
    B += zb * sBb + zh * sBh;
    C += zb * sCb + zh * sCh;

    const int m0  = blockIdx.y * BM;
    const int n0  = blockIdx.x * BN;
    const int tid = threadIdx.x;
    const int warp = tid >> 5;
    const int lane = tid & 31;
    const int gr  = lane >> 2;       // 0..7
    const int tg  = lane & 3;        // 0..3
    const int wm0 = (warp / WARPS_N) * WM;
    const int wn0 = (warp % WARPS_N) * WN;

    float acc[MT][NTt][4];
#pragma unroll
    for (int i = 0; i < MT; i++)
#pragma unroll
        for (int j = 0; j < NTt; j++)
#pragma unroll
            for (int q = 0; q < 4; q++) acc[i][j][q] = 0.0f;

    auto loadTiles = [&](int kt, int buf) {
        const int k0 = kt * BK;
        float* Asp = sm + buf * ASZ;
        float* Bsp = sm + 2 * ASZ + buf * BSZ;
#pragma unroll
        for (int r = 0; r < (BM * BK / 4) / NTH; r++) {
            int idx = r * NTH + tid;
            int m = idx / (BK / 4), k4 = idx % (BK / 4);
            cp16(&Asp[m * AP + k4 * 4], &A[(LL)(m0 + m) * lda + k0 + k4 * 4]);
        }
        if (TRANSB) {
#pragma unroll
            for (int r = 0; r < (BN * BK / 4) / NTH; r++) {
                int idx = r * NTH + tid;
                int n = idx / (BK / 4), k4 = idx % (BK / 4);
                cp16(&Bsp[n * BPt + k4 * 4], &B[(LL)(n0 + n) * ldb + k0 + k4 * 4]);
            }
        } else {
#pragma unroll
            for (int r = 0; r < (BK * BN / 4) / NTH; r++) {
                int idx = r * NTH + tid;
                int kk = idx / (BN / 4), n4 = idx % (BN / 4);
                cp16(&Bsp[kk * BPn + n4 * 4], &B[(LL)(k0 + kk) * ldb + n0 + n4 * 4]);
            }
        }
        cp_commit();
    };

    auto compute = [&](int buf) {
        const float* Asp = sm + buf * ASZ;
        const float* Bsp = sm + 2 * ASZ + buf * BSZ;
#pragma unroll
        for (int ks = 0; ks < BK; ks += 16) {
            unsigned ah[MT][4], al[MT][4], bh[NTt][2], bl[NTt][2];
#pragma unroll
            for (int mt = 0; mt < MT; mt++) {
                int m = wm0 + mt * 16;
                float2 p0 = *reinterpret_cast<const float2*>(&Asp[(m + gr)     * AP + ks + tg * 2]);
                float2 p1 = *reinterpret_cast<const float2*>(&Asp[(m + gr + 8) * AP + ks + tg * 2]);
                float2 p2 = *reinterpret_cast<const float2*>(&Asp[(m + gr)     * AP + ks + tg * 2 + 8]);
                float2 p3 = *reinterpret_cast<const float2*>(&Asp[(m + gr + 8) * AP + ks + tg * 2 + 8]);
                bf16x2_split(p0.x, p0.y, ah[mt][0], al[mt][0]);
                bf16x2_split(p1.x, p1.y, ah[mt][1], al[mt][1]);
                bf16x2_split(p2.x, p2.y, ah[mt][2], al[mt][2]);
                bf16x2_split(p3.x, p3.y, ah[mt][3], al[mt][3]);
            }
#pragma unroll
            for (int nt = 0; nt < NTt; nt++) {
                int n = wn0 + nt * 8;
                float y00, y01, y10, y11;
                if (TRANSB) {
                    float2 q0 = *reinterpret_cast<const float2*>(&Bsp[(n + gr) * BPt + ks + tg * 2]);
                    float2 q1 = *reinterpret_cast<const float2*>(&Bsp[(n + gr) * BPt + ks + tg * 2 + 8]);
                    y00 = q0.x; y01 = q0.y; y10 = q1.x; y11 = q1.y;
                } else {
                    y00 = Bsp[(ks + tg * 2)     * BPn + n + gr];
                    y01 = Bsp[(ks + tg * 2 + 1) * BPn + n + gr];
                    y10 = Bsp[(ks + tg * 2 + 8) * BPn + n + gr];
                    y11 = Bsp[(ks + tg * 2 + 9) * BPn + n + gr];
                }
                bf16x2_split(y00, y01, bh[nt][0], bl[nt][0]);
                bf16x2_split(y10, y11, bh[nt][1], bl[nt][1]);
            }
            // 3xBF16: hi*lo + lo*hi + hi*hi  (lo*lo ~2^-18, dropped)
#pragma unroll
            for (int mt = 0; mt < MT; mt++)
#pragma unroll
                for (int nt = 0; nt < NTt; nt++) {
                    mma_bf16(acc[mt][nt], ah[mt], bl[nt]);
                    mma_bf16(acc[mt][nt], al[mt], bh[nt]);
                    mma_bf16(acc[mt][nt], ah[mt], bh[nt]);
                }
        }
    };

    const int KT = K / BK;
    loadTiles(0, 0);
    for (int kt = 0; kt < KT; kt++) {
        cp_wait0();
        __syncthreads();
        if (kt + 1 < KT) loadTiles(kt + 1, (kt + 1) & 1);
        compute(kt & 1);
        __syncthreads();
    }

    // epilogue
#pragma unroll
    for (int mt = 0; mt < MT; mt++) {
        int r0 = m0 + wm0 + mt * 16 + gr;
#pragma unroll
        for (int nt = 0; nt < NTt; nt++) {
            int cc = n0 + wn0 + nt * 8 + tg * 2;
            float v0 = acc[mt][nt][0] * alpha;
            float v1 = acc[mt][nt][1] * alpha;
            float v2 = acc[mt][nt][2] * alpha;
            float v3 = acc[mt][nt][3] * alpha;
            if (bias) {
                float b0 = bias[cc], b1 = bias[cc + 1];
                v0 += b0; v1 += b1; v2 += b0; v3 += b1;
            }
            if (ACT == 1) {
                v0 = gelu_exact(v0); v1 = gelu_exact(v1);
                v2 = gelu_exact(v2); v3 = gelu_exact(v3);
            }
            float2 p0 = {v0, v1};
            float2 p1 = {v2, v3};
            *reinterpret_cast<float2*>(&C[(LL)r0 * ldc + cc]) = p0;
            *reinterpret_cast<float2*>(&C[(LL)(r0 + 8) * ldc + cc]) = p1;
        }
    }
}

// ---------------- softmax over rows of length 2048 ----------------
__global__ void softmax2048_k(float* __restrict__ sc)
{
    __shared__ float red[32];
    float* p = sc + (LL)blockIdx.x * 2048;
    const int tid = threadIdx.x;
    float v[8];
    float mx = -1e30f;
#pragma unroll
    for (int i = 0; i < 8; i++) { v[i] = p[tid + i * 256]; mx = fmaxf(mx, v[i]); }
#pragma unroll
    for (int o = 16; o > 0; o >>= 1) mx = fmaxf(mx, __shfl_xor_sync(0xffffffffu, mx, o));
    if ((tid & 31) == 0) red[tid >> 5] = mx;
    __syncthreads();
    if (tid < 32) {
        float t = (tid < 8) ? red[tid] : -1e30f;
#pragma unroll
        for (int o = 4; o > 0; o >>= 1) t = fmaxf(t, __shfl_xor_sync(0xffffffffu, t, o));
        if (tid == 0) red[0] = t;
    }
    __syncthreads();
    mx = red[0];
    __syncthreads();

    float s = 0.0f;
#pragma unroll
    for (int i = 0; i < 8; i++) { v[i] = __expf(v[i] - mx); s += v[i]; }
#pragma unroll
    for (int o = 16; o > 0; o >>= 1) s += __shfl_xor_sync(0xffffffffu, s, o);
    if ((tid & 31) == 0) red[tid >> 5] = s;
    __syncthreads();
    if (tid < 32) {
        float t = (tid < 8) ? red[tid] : 0.0f;
#pragma unroll
        for (int o = 4; o > 0; o >>= 1) t += __shfl_xor_sync(0xffffffffu, t, o);
        if (tid == 0) red[0] = t;
    }
    __syncthreads();
    float inv = 1.0f / red[0];
#pragma unroll
    for (int i = 0; i < 8; i++) p[tid + i * 256] = v[i] * inv;
}

// ---------------- residual add + layernorm ----------------
__global__ void add_ln_k(const float* __restrict__ x, const float* __restrict__ r,
                         const float* __restrict__ g, const float* __restrict__ b,
                         float* __restrict__ o)
{
    __shared__ float redS[8];
    __shared__ float redQ[8];
    const LL row = blockIdx.x;
    const float* px = x + row * DM;
    const float* pr = r ? (r + row * DM) : nullptr;
    const int tid = threadIdx.x;
    float v[4];
    float s = 0.0f, sq = 0.0f;
#pragma unroll
    for (int i = 0; i < 4; i++) {
        float t = px[tid + i * 256];
        if (pr) t += pr[tid + i * 256];
        v[i] = t;
        s += t;
        sq = fmaf(t, t, sq);
    }
#pragma unroll
    for (int off = 16; off > 0; off >>= 1) {
        s  += __shfl_xor_sync(0xffffffffu, s,  off);
        sq += __shfl_xor_sync(0xffffffffu, sq, off);
    }
    if ((tid & 31) == 0) { redS[tid >> 5] = s; redQ[tid >> 5] = sq; }
    __syncthreads();
    if (tid < 32) {
        float ts = (tid < 8) ? redS[tid] : 0.0f;
        float tq = (tid < 8) ? redQ[tid] : 0.0f;
#pragma unroll
        for (int off = 4; off > 0; off >>= 1) {
            ts += __shfl_xor_sync(0xffffffffu, ts, off);
            tq += __shfl_xor_sync(0xffffffffu, tq, off);
        }
        if (tid == 0) { redS[0] = ts; redQ[0] = tq; }
    }
    __syncthreads();
    const float mean = redS[0] * (1.0f / DM);
    const float var  = redQ[0] * (1.0f / DM) - mean * mean;
    const float rstd = rsqrtf(var + 1e-5f);
    float* po = o + row * DM;
#pragma unroll
    for (int i = 0; i < 4; i++) {
        int d = tid + i * 256;
        po[d] = (v[i] - mean) * rstd * g[d] + b[d];
    }
}

// ---------------- embedding + positional ----------------
__global__ void embed_k(const int* __restrict__ ids, const float* __restrict__ emb,
                        const float* __restrict__ pe, float* __restrict__ h)
{
    int idx = blockIdx.x * 256 + threadIdx.x;
    int t = idx >> 10;
    int d = idx & 1023;
    int sp = t & (SS - 1);
    h[idx] = 2.0f * emb[(LL)ids[t] * DM + d] + pe[(LL)sp * DM + d];
}

// ---------------- host driver ----------------
extern "C" void kernel_launch(void* const* d_in, const int* in_sizes, int n_in,
                              void* d_out, int out_size)
{
    (void)in_sizes; (void)n_in; (void)out_size;

    const int*   ids  = (const int*)  d_in[0];
    const float* emb  = (const float*)d_in[1];
    const float* pe   = (const float*)d_in[2];
    const float* wq   = (const float*)d_in[3];
    const float* bq   = (const float*)d_in[4];
    const float* wk   = (const float*)d_in[5];
    const float* bk   = (const float*)d_in[6];
    const float* wv   = (const float*)d_in[7];
    const float* bv   = (const float*)d_in[8];
    const float* wo   = (const float*)d_in[9];
    const float* bo   = (const float*)d_in[10];
    const float* ln1g = (const float*)d_in[11];
    const float* ln1b = (const float*)d_in[12];
    const float* w1   = (const float*)d_in[13];
    const float* b1   = (const float*)d_in[14];
    const float* w2   = (const float*)d_in[15];
    const float* b2   = (const float*)d_in[16];
    const float* ln2g = (const float*)d_in[17];
    const float* ln2b = (const float*)d_in[18];
    const float* lnfg = (const float*)d_in[19];
    const float* lnfb = (const float*)d_in[20];
    const float* lmh  = (const float*)d_in[21];
    float* out = (float*)d_out;

    float *h, *tmp, *q, *k, *v, *ctx, *hn, *ffn, *sc;
    cudaGetSymbolAddress((void**)&h,   g_h);
    cudaGetSymbolAddress((void**)&tmp, g_tmp);
    cudaGetSymbolAddress((void**)&q,   g_q);
    cudaGetSymbolAddress((void**)&k,   g_k);
    cudaGetSymbolAddress((void**)&v,   g_v);
    cudaGetSymbolAddress((void**)&ctx, g_ctx);
    cudaGetSymbolAddress((void**)&hn,  g_hn);
    cudaGetSymbolAddress((void**)&ffn, g_ffn);
    cudaGetSymbolAddress((void**)&sc,  g_scores);

    embed_k<<<(NT * DM) / 256, 256>>>(ids, emb, pe, h);

    const float scale = 1.0f / 8.0f;

    for (int i = 0; i < LAYERS; i++) {
        const float* wqi = wq + (LL)i * DM * DM;  const float* bqi = bq + (LL)i * DM;
        const float* wki = wk + (LL)i * DM * DM;  const float* bki = bk + (LL)i * DM;
        const float* wvi = wv + (LL)i * DM * DM;  const float* bvi = bv + (LL)i * DM;
        const float* woi = wo + (LL)i * DM * DM;  const float* boi = bo + (LL)i * DM;
        const float* w1i = w1 + (LL)i * DM * FF;  const float* b1i = b1 + (LL)i * FF;
        const float* w2i = w2 + (LL)i * FF * DM;  const float* b2i = b2 + (LL)i * DM;

        // Q/K/V projections
        {
            dim3 grid(DM / 128, NT / 128, 1);
            mma_gemm<128,128,16,64,32,false,0><<<grid, 256>>>(h, wqi, bqi, q, DM, DM, DM, DM, 1.0f,
                                                              1, 0,0, 0,0, 0,0);
            mma_gemm<128,128,16,64,32,false,0><<<grid, 256>>>(h, wki, bki, k, DM, DM, DM, DM, 1.0f,
                                                              1, 0,0, 0,0, 0,0);
            mma_gemm<128,128,16,64,32,false,0><<<grid, 256>>>(h, wvi, bvi, v, DM, DM, DM, DM, 1.0f,
                                                              1, 0,0, 0,0, 0,0);
        }

        // scores[z] = scale * Qh @ Kh^T
        {
            dim3 grid(SS / 128, SS / 128, BB * NH);
            mma_gemm<128,128,16,64,32,true,0><<<grid, 256>>>(
                q, k, nullptr, sc, HD, DM, DM, SS, scale,
                NH, (LL)SS * DM, HD, (LL)SS * DM, HD,
                (LL)NH * SS * SS, (LL)SS * SS);
        }

        softmax2048_k<<<BB * NH * SS, 256>>>(sc);

        // ctx[z] = P @ Vh
        {
            dim3 grid(HD / 64, SS / 128, BB * NH);
            mma_gemm<128,64,16,32,32,false,0><<<grid, 256>>>(
                sc, v, nullptr, ctx, SS, SS, DM, DM, 1.0f,
                NH, (LL)NH * SS * SS, (LL)SS * SS,
                (LL)SS * DM, HD, (LL)SS * DM, HD);
        }

        // attn_out = ctx @ wo + bo
        {
            dim3 grid(DM / 128, NT / 128, 1);
            mma_gemm<128,128,16,64,32,false,0><<<grid, 256>>>(ctx, woi, boi, tmp, DM, DM, DM, DM, 1.0f,
                                                              1, 0,0, 0,0, 0,0);
        }
        add_ln_k<<<NT, 256>>>(h, tmp, ln1g + (LL)i * DM, ln1b + (LL)i * DM, h);

        // ffn1 = gelu(h @ w1 + b1)
        {
            dim3 grid(FF / 128, NT / 128, 1);
            mma_gemm<128,128,16,64,32,false,1><<<grid, 256>>>(h, w1i, b1i, ffn, DM, DM, FF, FF, 1.0f,
                                                              1, 0,0, 0,0, 0,0);
        }
        // ffn2 = ffn1 @ w2 + b2
        {
            dim3 grid(DM / 128, NT / 128, 1);
            mma_gemm<128,128,16,64,32,false,0><<<grid, 256>>>(ffn, w2i, b2i, tmp, FF, FF, DM, DM, 1.0f,
                                                              1, 0,0, 0,0, 0,0);
        }
        add_ln_k<<<NT, 256>>>(h, tmp, ln2g + (LL)i * DM, ln2b + (LL)i * DM, h);
    }

    add_ln_k<<<NT, 256>>>(h, nullptr, lnfg, lnfb, hn);

    // logits = hn @ lm_head
    {
        dim3 grid(VOC / 128, NT / 128, 1);
        mma_gemm<128,128,16,64,32,false,0><<<grid, 256>>>(hn, lmh, nullptr, out, DM, DM, VOC, VOC, 1.0f,
                                                          1, 0,0, 0,0, 0,0);
    }
}